// round 14
// baseline (speedup 1.0000x reference)
#include <cuda_runtime.h>
#include <cuda_pipeline.h>
#include <math.h>

// Problem constants
#define BB    1024
#define LL    1024
#define NCAT  20
#define NNUM  10
#define EE    32
#define HH    256
#define TOPK  30
#define ROWS  8

typedef unsigned long long ull;

__device__ __forceinline__ ull pack2s(float v) {
    ull r; asm("mov.b64 %0, {%1, %1};" : "=l"(r) : "f"(v)); return r;
}
__device__ __forceinline__ ull pack2(float a, float b) {
    ull r; asm("mov.b64 %0, {%1, %2};" : "=l"(r) : "f"(a), "f"(b)); return r;
}
__device__ __forceinline__ void unpack2(ull p, float& a, float& b) {
    asm("mov.b64 {%0, %1}, %2;" : "=f"(a), "=f"(b) : "l"(p));
}
#define FMA2(d, a, b, c) asm("fma.rn.f32x2 %0, %1, %2, %3;" : "=l"(d) : "l"(a), "l"(b), "l"(c))
#define MUL2(d, a, b)    asm("mul.rn.f32x2 %0, %1, %2;"     : "=l"(d) : "l"(a), "l"(b))
#define ADD2(d, a, b)    asm("add.rn.f32x2 %0, %1, %2;"     : "=l"(d) : "l"(a), "l"(b))

// Device scratch
__device__ float g_fused[BB * 128];
__device__ float g_Wqk[EE * EE];
__device__ float g_Wvo[EE * EE];

// ---------------------------------------------------------------------------
// Precompute fused 32x32 matrices (unchanged).
// ---------------------------------------------------------------------------
__global__ __launch_bounds__(256)
void precompute_kernel(const float* __restrict__ Wq,
                       const float* __restrict__ Wk,
                       const float* __restrict__ Wv,
                       const float* __restrict__ Wo) {
    __shared__ float sA[32 * 128];
    __shared__ float sB[128 * 33];
    int tid = threadIdx.x;

    if (blockIdx.x == 0) {
        for (int i = tid; i < 4096; i += 256) sA[i] = Wq[i];
        for (int i = tid; i < 4096; i += 256) {
            int e2 = i >> 7, a = i & 127;
            sB[a * 33 + e2] = Wk[i];
        }
        __syncthreads();
        for (int o = tid; o < 1024; o += 256) {
            int e1 = o >> 5, e2 = o & 31;
            float s = 0.f;
#pragma unroll 8
            for (int a = 0; a < 128; a++)
                s += sA[e1 * 128 + a] * sB[a * 33 + e2];
            g_Wqk[o] = s * 0.08838834764831845f;
        }
    } else {
        for (int i = tid; i < 4096; i += 256) sA[i] = Wv[i];
        for (int i = tid; i < 4096; i += 256) {
            int a = i >> 5, e2 = i & 31;
            sB[a * 33 + e2] = Wo[i];
        }
        __syncthreads();
        for (int o = tid; o < 1024; o += 256) {
            int e1 = o >> 5, e2 = o & 31;
            float s = 0.f;
#pragma unroll 8
            for (int a = 0; a < 128; a++)
                s += sA[e1 * 128 + a] * sB[a * 33 + e2];
            g_Wvo[o] = s;
        }
    }
}

// ---------------------------------------------------------------------------
// Fused front + attention kernel. Phase A now produces order-preserving keys
// directly and builds the histogram inline (one pass, one fewer barrier).
// ---------------------------------------------------------------------------
__device__ __forceinline__ unsigned score_key(float f) {
    unsigned u = __float_as_uint(f);
    return u ^ (((int)u >> 31) | 0x80000000u);
}
__device__ __forceinline__ float key_to_float(unsigned key) {
    unsigned u = (key & 0x80000000u) ? (key ^ 0x80000000u) : ~key;
    return __uint_as_float(u);
}

__global__ __launch_bounds__(256, 7)
void fa_kernel(const int* __restrict__ cats,
               const float* __restrict__ nums,
               const int* __restrict__ seqs,
               const int* __restrict__ tgt_ids,
               const float* __restrict__ cat_emb,
               const float* __restrict__ seq_emb,
               const float* __restrict__ Wnum,
               const float* __restrict__ bnum,
               const float* __restrict__ Wpool,
               const float* __restrict__ bpool,
               const float* __restrict__ bo) {
    int b = blockIdx.x;
    int tid  = threadIdx.x;
    int lane = tid & 31, warp = tid >> 5;
    __shared__ unsigned s_skey[LL];
    __shared__ int      s_hist[1024];      // aliased as s_ckey after phase C
    __shared__ int      s_cidx[1024];
    __shared__ float    s_cat[NCAT * EE];
    __shared__ float    s_tgt[EE];
    __shared__ float    s_part[8][EE];
    __shared__ float    s_qk[EE];
    __shared__ float    s_val[TOPK];
    __shared__ int      s_sel[TOPK];
    __shared__ float    s_w[TOPK];
    __shared__ float    s_pp[8][EE];
    __shared__ int      s_cnt;
    __shared__ int      s_thr;

    for (int i = tid; i < NCAT * EE; i += 256)
        s_cat[i] = cat_emb[(long)cats[b * NCAT + (i >> 5)] * EE + (i & 31)];
    if (tid < EE)
        s_tgt[tid] = cat_emb[(long)tgt_ids[b] * EE + tid];
    for (int i = tid; i < 1024; i += 256) s_hist[i] = 0;
    if (tid == 0) s_cnt = 0;
    __syncthreads();

    {
        int e = tid & 31, p = tid >> 5;
        float acc = 0.f;
#pragma unroll 4
        for (int i = p * 80; i < (p + 1) * 80; i++)
            acc += s_cat[i] * Wpool[i * EE + e];
        s_part[p][e] = acc;
    }
    __syncthreads();

    if (tid < EE) {
        int e = tid;
        float cp = bpool[e];
#pragma unroll
        for (int p = 0; p < 8; p++) cp += s_part[p][e];
        float ne = bnum[e];
#pragma unroll
        for (int j = 0; j < NNUM; j++) ne += nums[b * NNUM + j] * Wnum[j * EE + e];
        float qk = 0.f;
#pragma unroll
        for (int e2 = 0; e2 < EE; e2++) qk += s_tgt[e2] * g_Wqk[e2 * EE + e];
        float* fr = g_fused + (long)b * 128;
        fr[e]      = s_tgt[e];
        fr[64 + e] = cp;
        fr[96 + e] = ne;
        s_qk[e] = qk;
    }
    __syncthreads();

    const int* srow = seqs + (long)b * LL;

    // Phase A: scores -> keys + inline histogram
    {
        int g = tid >> 3;
        int c = tid & 7;
        float qk4[4] = { s_qk[c * 4 + 0], s_qk[c * 4 + 1], s_qk[c * 4 + 2], s_qk[c * 4 + 3] };
#pragma unroll 8
        for (int l0 = 0; l0 < LL; l0 += 32) {
            int l = l0 + g;
            int id = srow[l];
            float4 v = reinterpret_cast<const float4*>(seq_emb + (long)id * EE)[c];
            float s = qk4[0] * v.x + qk4[1] * v.y + qk4[2] * v.z + qk4[3] * v.w;
            s += __shfl_down_sync(0xffffffffu, s, 4, 8);
            s += __shfl_down_sync(0xffffffffu, s, 2, 8);
            s += __shfl_down_sync(0xffffffffu, s, 1, 8);
            if (c == 0) {
                unsigned key = score_key(s);
                s_skey[l] = key;
                atomicAdd(&s_hist[key >> 22], 1);
            }
        }
    }
    __syncthreads();

    // Phase C: threshold bin (warp 0)
    if (warp == 0) {
        int base = 1024 - (lane + 1) * 32;
        int s = 0;
#pragma unroll
        for (int i = 0; i < 32; i++) s += s_hist[base + i];
        int pre = s;
#pragma unroll
        for (int off = 1; off < 32; off <<= 1) {
            int o = __shfl_up_sync(0xffffffffu, pre, off);
            if (lane >= off) pre += o;
        }
        int preExcl = pre - s;
        if (pre >= TOPK && preExcl < TOPK) {
            int cum = preExcl;
            for (int i = 31; i >= 0; i--) {
                cum += s_hist[base + i];
                if (cum >= TOPK) { s_thr = base + i; break; }
            }
        }
    }
    __syncthreads();

    // Phase D: compact candidates (keys already stored)
    unsigned* s_ckey = (unsigned*)s_hist;
    unsigned thrkey = (unsigned)s_thr << 22;
    for (int i = tid; i < LL; i += 256) {
        unsigned key = s_skey[i];
        if (key >= thrkey) {
            int p = atomicAdd(&s_cnt, 1);
            s_ckey[p] = key;
            s_cidx[p] = i;
        }
    }
    __syncthreads();

    // Phase E: exact top-30 (warp 0, REDUX, tiebreak = min idx)
    if (warp == 0) {
        int m = s_cnt;
        if (m <= 96) {
            unsigned k0 = 0, k1 = 0, k2 = 0;
            unsigned i0 = 0xffffffffu, i1 = 0xffffffffu, i2 = 0xffffffffu;
            if (lane < m)      { k0 = s_ckey[lane];      i0 = (unsigned)s_cidx[lane]; }
            if (lane + 32 < m) { k1 = s_ckey[lane + 32]; i1 = (unsigned)s_cidx[lane + 32]; }
            if (lane + 64 < m) { k2 = s_ckey[lane + 64]; i2 = (unsigned)s_cidx[lane + 64]; }
#pragma unroll 1
            for (int k = 0; k < TOPK; k++) {
                unsigned bk = k0, bi = i0; int slot = 0;
                if (k1 > bk || (k1 == bk && i1 < bi)) { bk = k1; bi = i1; slot = 1; }
                if (k2 > bk || (k2 == bk && i2 < bi)) { bk = k2; bi = i2; slot = 2; }
                unsigned mxk = __reduce_max_sync(0xffffffffu, bk);
                unsigned cand = (bk == mxk) ? bi : 0xffffffffu;
                unsigned mni = __reduce_min_sync(0xffffffffu, cand);
                if (lane == 0) { s_val[k] = key_to_float(mxk); s_sel[k] = (int)mni; }
                if (bk == mxk && bi == mni) {
                    if (slot == 0)      { k0 = 0; i0 = 0xffffffffu; }
                    else if (slot == 1) { k1 = 0; i1 = 0xffffffffu; }
                    else                { k2 = 0; i2 = 0xffffffffu; }
                }
            }
        } else {
#pragma unroll 1
            for (int k = 0; k < TOPK; k++) {
                unsigned bk = 0, bi = 0xffffffffu; int bp = -1;
                for (int p = lane; p < m; p += 32) {
                    unsigned key = s_ckey[p]; unsigned ix = (unsigned)s_cidx[p];
                    if (key > bk || (key == bk && ix < bi)) { bk = key; bi = ix; bp = p; }
                }
                unsigned mxk = __reduce_max_sync(0xffffffffu, bk);
                unsigned cand = (bk == mxk) ? bi : 0xffffffffu;
                unsigned mni = __reduce_min_sync(0xffffffffu, cand);
                if (lane == 0) { s_val[k] = key_to_float(mxk); s_sel[k] = (int)mni; }
                if (bk == mxk && bi == mni) s_ckey[bp] = 0;
                __syncwarp();
            }
        }
        float mx = s_val[0];
        float e = (lane < TOPK) ? __expf(s_val[lane] - mx) : 0.f;
        float sum = e;
#pragma unroll
        for (int off = 16; off; off >>= 1) sum += __shfl_xor_sync(0xffffffffu, sum, off);
        if (lane < TOPK) s_w[lane] = e / sum;
    }
    __syncthreads();

    // Phase F: pooled + interest
    {
        float p = 0.f;
        for (int k = warp; k < TOPK; k += 8)
            p += s_w[k] * seq_emb[(long)srow[s_sel[k]] * EE + lane];
        s_pp[warp][lane] = p;
    }
    __syncthreads();

    if (tid < EE) {
        float p = s_pp[0][tid] + s_pp[1][tid] + s_pp[2][tid] + s_pp[3][tid] +
                  s_pp[4][tid] + s_pp[5][tid] + s_pp[6][tid] + s_pp[7][tid];
        s_pp[0][tid] = p;
    }
    __syncthreads();
    if (tid < EE) {
        float acc = bo[tid];
#pragma unroll
        for (int e = 0; e < EE; e++) acc += s_pp[0][e] * g_Wvo[e * EE + tid];
        g_fused[(long)b * 128 + EE + tid] = acc;
    }
}

// ---------------------------------------------------------------------------
// MLP tail: 512 threads = 8 pairs x 2 warps. 3-STAGE per-warp weight pipeline
// (16-row single / 8-row dual tiles, 2KB each) -> two tiles in flight cover
// L2 latency. No barriers in mainloops; pairs sync only at reductions.
// ---------------------------------------------------------------------------
#define WT 512   // floats per stage per warp (2KB)

__device__ __forceinline__ void barpair(int pair) {
    asm volatile("bar.sync %0, 64;" :: "r"(pair + 1) : "memory");
}

// single tile: rows [kbase + t*16, +16), cols [wcol0,+32); one warp fills.
__device__ __forceinline__ void fill_s16(const float* __restrict__ W, float* dst,
                                         int wcol0, int kbase, int t, int lane) {
#pragma unroll
    for (int it = 0; it < 4; it++) {
        int c = it * 32 + lane;             // 128 chunks of 16B
        int row = c >> 3, c4 = (c & 7) * 4;
        __pipeline_memcpy_async(dst + row * 32 + c4,
                                W + (kbase + t * 16 + row) * 256 + wcol0 + c4, 16);
    }
}
// dual tile: rows [kbase + t*8, +8) of Wa and Wb; one warp fills.
__device__ __forceinline__ void fill_d8(const float* __restrict__ Wa,
                                        const float* __restrict__ Wb, float* dst,
                                        int wcol0, int kbase, int t, int lane) {
#pragma unroll
    for (int it = 0; it < 4; it++) {
        int c = it * 32 + lane;
        int m = c >> 6, cr = c & 63;
        int row = cr >> 3, c4 = (cr & 7) * 4;
        const float* src = m ? Wb : Wa;
        __pipeline_memcpy_async(dst + m * 256 + row * 32 + c4,
                                src + (kbase + t * 8 + row) * 256 + wcol0 + c4, 16);
    }
}

__device__ __forceinline__ void pro_s(const float* __restrict__ W, float* wbuf,
                                      int wcol0, int kbase, int lane) {
    fill_s16(W, wbuf, wcol0, kbase, 0, lane);
    __pipeline_commit();
    fill_s16(W, wbuf + WT, wcol0, kbase, 1, lane);
    __pipeline_commit();
}
__device__ __forceinline__ void pro_d(const float* __restrict__ Wa,
                                      const float* __restrict__ Wb, float* wbuf,
                                      int wcol0, int kbase, int lane) {
    fill_d8(Wa, Wb, wbuf, wcol0, kbase, 0, lane);
    __pipeline_commit();
    fill_d8(Wa, Wb, wbuf + WT, wcol0, kbase, 1, lane);
    __pipeline_commit();
}

// entry: tiles 0,1 prefetched + committed by this warp
template<int Kw>   // this warp's K-range
__device__ __forceinline__ void gemm_s(const float* __restrict__ W,
                                       const float* s_x, float* wbuf,
                                       int wcol0, int kbase, int lane, ull acc[4]) {
    constexpr int T = Kw / 16;
#pragma unroll
    for (int t = 0; t < T; t++) {
        if (t + 2 < T) {
            fill_s16(W, wbuf + ((t + 2) % 3) * WT, wcol0, kbase, t + 2, lane);
            __pipeline_commit();
            __pipeline_wait_prior(2);
        } else if (t + 1 < T) {
            __pipeline_wait_prior(1);
        } else {
            __pipeline_wait_prior(0);
        }
        __syncwarp();
        const float* bw = wbuf + (t % 3) * WT;
        const float* xs = s_x + (kbase + t * 16) * 8;
#pragma unroll
        for (int i = 0; i < 16; i++) {
            ulonglong2 xa = *(const ulonglong2*)(xs + i * 8);
            ulonglong2 xb = *(const ulonglong2*)(xs + i * 8 + 4);
            ull wp = pack2s(bw[i * 32 + lane]);
            FMA2(acc[0], xa.x, wp, acc[0]);
            FMA2(acc[1], xa.y, wp, acc[1]);
            FMA2(acc[2], xb.x, wp, acc[2]);
            FMA2(acc[3], xb.y, wp, acc[3]);
        }
    }
}

__device__ __forceinline__ void gemm_d(const float* __restrict__ Wa,
                                       const float* __restrict__ Wb,
                                       const float* s_x, float* wbuf,
                                       int wcol0, int kbase, int lane,
                                       ull a1[4], ull a2[4]) {
    constexpr int T = 16;   // warp K-range 128, 8 rows per tile
#pragma unroll
    for (int t = 0; t < T; t++) {
        if (t + 2 < T) {
            fill_d8(Wa, Wb, wbuf + ((t + 2) % 3) * WT, wcol0, kbase, t + 2, lane);
            __pipeline_commit();
            __pipeline_wait_prior(2);
        } else if (t + 1 < T) {
            __pipeline_wait_prior(1);
        } else {
            __pipeline_wait_prior(0);
        }
        __syncwarp();
        const float* bwa = wbuf + (t % 3) * WT;
        const float* bwb = bwa + 256;
        const float* xs = s_x + (kbase + t * 8) * 8;
#pragma unroll
        for (int i = 0; i < 8; i++) {
            ulonglong2 xa = *(const ulonglong2*)(xs + i * 8);
            ulonglong2 xb = *(const ulonglong2*)(xs + i * 8 + 4);
            ull w1 = pack2s(bwa[i * 32 + lane]);
            ull w2 = pack2s(bwb[i * 32 + lane]);
            FMA2(a1[0], xa.x, w1, a1[0]);
            FMA2(a1[1], xa.y, w1, a1[1]);
            FMA2(a1[2], xb.x, w1, a1[2]);
            FMA2(a1[3], xb.y, w1, a1[3]);
            FMA2(a2[0], xa.x, w2, a2[0]);
            FMA2(a2[1], xa.y, w2, a2[1]);
            FMA2(a2[2], xb.x, w2, a2[2]);
            FMA2(a2[3], xb.y, w2, a2[3]);
        }
    }
}

__global__ __launch_bounds__(512)
void mlp_kernel(const float* __restrict__ Wmlp, const float* __restrict__ bmlp,
                const float* __restrict__ W11, const float* __restrict__ b11,
                const float* __restrict__ W12, const float* __restrict__ b12,
                const float* __restrict__ W1p, const float* __restrict__ b1p,
                const float* __restrict__ W21, const float* __restrict__ b21,
                const float* __restrict__ W22, const float* __restrict__ b22,
                const float* __restrict__ W2p, const float* __restrict__ b2p,
                const float* __restrict__ Wout, const float* __restrict__ bout,
                float* __restrict__ out) {
    extern __shared__ float smem[];
    float* s_f = smem;                 // 128*8 interleaved [i][r]
    float* s_h = smem + 1024;          // 256*8 interleaved
    float* s_q = s_h + 2048;
    float* wall = s_q + 2048;          // 16 warps * 3 * WT = 24576 floats
    ull*   red  = (ull*)(wall + 16 * 3 * WT);   // 256 cols * 8 ull = 16KB

    int b0 = blockIdx.x * ROWS;
    int tid = threadIdx.x;
    int w = tid >> 5, lane = tid & 31;
    int pair = w >> 1, sub = w & 1;
    int wcol0 = pair * 32;
    int colg = wcol0 + lane;
    float* wbuf = wall + w * (3 * WT);             // per-WARP private buffers
    ull* redc = red + (pair * 32 + lane) * 8;

    for (int idx = tid; idx < ROWS * 128; idx += 512) {
        int r = idx >> 7, i = idx & 127;
        s_f[i * 8 + r] = g_fused[(long)b0 * 128 + idx];
    }
    pro_s(Wmlp, wbuf, wcol0, sub * 64, lane);
    __syncthreads();

    // h = relu(fused @ Wmlp + bmlp)   (warp K-range 64)
    {
        ull acc[4];
        ull bp = sub ? 0ull : pack2s(bmlp[colg]);
#pragma unroll
        for (int p = 0; p < 4; p++) acc[p] = bp;
        gemm_s<64>(Wmlp, s_f, wbuf, wcol0, sub * 64, lane, acc);
        if (sub) {
#pragma unroll
            for (int p = 0; p < 4; p++) redc[p] = acc[p];
        }
        barpair(pair);
        if (!sub) {
#pragma unroll
            for (int p = 0; p < 4; p++) {
                ADD2(acc[p], acc[p], redc[p]);
                float a, b;
                unpack2(acc[p], a, b);
                *(ull*)(s_h + colg * 8 + 2 * p) = pack2(fmaxf(a, 0.f), fmaxf(b, 0.f));
            }
        }
    }

    const float* Ws1[2] = { W11, W21 };  const float* Bs1[2] = { b11, b21 };
    const float* Ws2[2] = { W12, W22 };  const float* Bs2[2] = { b12, b22 };
    const float* Wsp[2] = { W1p, W2p };  const float* Bsp[2] = { b1p, b2p };

#pragma unroll
    for (int blk = 0; blk < 2; blk++) {
        pro_d(Ws1[blk], Ws2[blk], wbuf, wcol0, sub * 128, lane);
        __syncthreads();   // publishes s_h

        ull a1[4], a2[4];
        ull bb1 = sub ? 0ull : pack2s(Bs1[blk][colg]);
        ull bb2 = sub ? 0ull : pack2s(Bs2[blk][colg]);
#pragma unroll
        for (int p = 0; p < 4; p++) { a1[p] = bb1; a2[p] = bb2; }
        gemm_d(Ws1[blk], Ws2[blk], s_h, wbuf, wcol0, sub * 128, lane, a1, a2);
        if (sub) {
#pragma unroll
            for (int p = 0; p < 4; p++) { redc[p] = a1[p]; redc[4 + p] = a2[p]; }
        }
        barpair(pair);
        if (!sub) {
#pragma unroll
            for (int p = 0; p < 4; p++) {
                ADD2(a1[p], a1[p], redc[p]);
                ADD2(a2[p], a2[p], redc[4 + p]);
                ull qp;
                MUL2(qp, a1[p], a2[p]);
                *(ull*)(s_q + colg * 8 + 2 * p) = qp;
            }
        }

        pro_s(Wsp[blk], wbuf, wcol0, sub * 128, lane);
        __syncthreads();   // publishes s_q

        ull ap[4];
        ull bbp = sub ? 0ull : pack2s(Bsp[blk][colg]);
#pragma unroll
        for (int p = 0; p < 4; p++) ap[p] = bbp;
        gemm_s<128>(Wsp[blk], s_q, wbuf, wcol0, sub * 128, lane, ap);
        if (sub) {
#pragma unroll
            for (int p = 0; p < 4; p++) redc[p] = ap[p];
        }
        barpair(pair);
        if (!sub) {
#pragma unroll
            for (int p = 0; p < 4; p++) {
                ADD2(ap[p], ap[p], redc[p]);
                ull hp = *(ull*)(s_h + colg * 8 + 2 * p);
                ADD2(hp, hp, ap[p]);
                *(ull*)(s_h + colg * 8 + 2 * p) = hp;
            }
        }
    }
    __syncthreads();

    // out[b0+r] = sum_c h[r][c]*Wout[c] + bout (warps 0..7 reduce rows 0..7)
    if (w < 8) {
        float v = 0.f;
#pragma unroll
        for (int c = lane; c < HH; c += 32) v += s_h[c * 8 + w] * Wout[c];
#pragma unroll
        for (int off = 16; off; off >>= 1) v += __shfl_down_sync(0xffffffffu, v, off);
        if (lane == 0) out[b0 + w] = v + bout[0];
    }
}

// ---------------------------------------------------------------------------
extern "C" void kernel_launch(void* const* d_in, const int* in_sizes, int n_in,
                              void* d_out, int out_size) {
    const int*   cats    = (const int*)  d_in[0];
    const float* nums    = (const float*)d_in[1];
    const int*   seqs    = (const int*)  d_in[2];
    const int*   tgt_ids = (const int*)  d_in[3];
    const float* cat_emb = (const float*)d_in[4];
    const float* seq_emb = (const float*)d_in[5];
    const float* Wnum    = (const float*)d_in[6];
    const float* bnum    = (const float*)d_in[7];
    const float* Wq      = (const float*)d_in[8];
    const float* Wk      = (const float*)d_in[9];
    const float* Wv      = (const float*)d_in[10];
    const float* Wo      = (const float*)d_in[11];
    const float* bo      = (const float*)d_in[12];
    const float* Wpool   = (const float*)d_in[13];
    const float* bpool   = (const float*)d_in[14];
    const float* Wmlp    = (const float*)d_in[15];
    const float* bmlp    = (const float*)d_in[16];
    const float* q1_W1   = (const float*)d_in[17];
    const float* q1_b1   = (const float*)d_in[18];
    const float* q1_W2   = (const float*)d_in[19];
    const float* q1_b2   = (const float*)d_in[20];
    const float* q1_Wp   = (const float*)d_in[21];
    const float* q1_bp   = (const float*)d_in[22];
    const float* q2_W1   = (const float*)d_in[23];
    const float* q2_b1   = (const float*)d_in[24];
    const float* q2_W2   = (const float*)d_in[25];
    const float* q2_b2   = (const float*)d_in[26];
    const float* q2_Wp   = (const float*)d_in[27];
    const float* q2_bp   = (const float*)d_in[28];
    const float* Wout    = (const float*)d_in[29];
    const float* bout    = (const float*)d_in[30];
    float* out = (float*)d_out;

    const int mlp_smem = (1024 + 2048 + 2048 + 16 * 3 * WT) * sizeof(float) + 16384;
    cudaFuncSetAttribute(mlp_kernel, cudaFuncAttributeMaxDynamicSharedMemorySize, mlp_smem);

    precompute_kernel<<<2, 256>>>(Wq, Wk, Wv, Wo);
    fa_kernel<<<BB, 256>>>(cats, nums, seqs, tgt_ids, cat_emb, seq_emb,
                           Wnum, bnum, Wpool, bpool, bo);
    mlp_kernel<<<BB / ROWS, 512, mlp_smem>>>(
        Wmlp, bmlp,
        q1_W1, q1_b1, q1_W2, q1_b2, q1_Wp, q1_bp,
        q2_W1, q2_b1, q2_W2, q2_b2, q2_Wp, q2_bp,
        Wout, bout, out);
}

// round 15
// speedup vs baseline: 1.0916x; 1.0916x over previous
#include <cuda_runtime.h>
#include <cuda_pipeline.h>
#include <math.h>

// Problem constants
#define BB    1024
#define LL    1024
#define NCAT  20
#define NNUM  10
#define EE    32
#define HH    256
#define TOPK  30
#define ROWS  8

typedef unsigned long long ull;

__device__ __forceinline__ ull pack2s(float v) {
    ull r; asm("mov.b64 %0, {%1, %1};" : "=l"(r) : "f"(v)); return r;
}
__device__ __forceinline__ ull pack2(float a, float b) {
    ull r; asm("mov.b64 %0, {%1, %2};" : "=l"(r) : "f"(a), "f"(b)); return r;
}
__device__ __forceinline__ void unpack2(ull p, float& a, float& b) {
    asm("mov.b64 {%0, %1}, %2;" : "=f"(a), "=f"(b) : "l"(p));
}
#define FMA2(d, a, b, c) asm("fma.rn.f32x2 %0, %1, %2, %3;" : "=l"(d) : "l"(a), "l"(b), "l"(c))
#define MUL2(d, a, b)    asm("mul.rn.f32x2 %0, %1, %2;"     : "=l"(d) : "l"(a), "l"(b))
#define ADD2(d, a, b)    asm("add.rn.f32x2 %0, %1, %2;"     : "=l"(d) : "l"(a), "l"(b))

// Device scratch
__device__ float g_fused[BB * 128];
__device__ float g_Wqk[EE * EE];
__device__ float g_Wvo[EE * EE];

// ---------------------------------------------------------------------------
// Precompute fused 32x32 matrices (unchanged).
// ---------------------------------------------------------------------------
__global__ __launch_bounds__(256)
void precompute_kernel(const float* __restrict__ Wq,
                       const float* __restrict__ Wk,
                       const float* __restrict__ Wv,
                       const float* __restrict__ Wo) {
    __shared__ float sA[32 * 128];
    __shared__ float sB[128 * 33];
    int tid = threadIdx.x;

    if (blockIdx.x == 0) {
        for (int i = tid; i < 4096; i += 256) sA[i] = Wq[i];
        for (int i = tid; i < 4096; i += 256) {
            int e2 = i >> 7, a = i & 127;
            sB[a * 33 + e2] = Wk[i];
        }
        __syncthreads();
        for (int o = tid; o < 1024; o += 256) {
            int e1 = o >> 5, e2 = o & 31;
            float s = 0.f;
#pragma unroll 8
            for (int a = 0; a < 128; a++)
                s += sA[e1 * 128 + a] * sB[a * 33 + e2];
            g_Wqk[o] = s * 0.08838834764831845f;
        }
    } else {
        for (int i = tid; i < 4096; i += 256) sA[i] = Wv[i];
        for (int i = tid; i < 4096; i += 256) {
            int a = i >> 5, e2 = i & 31;
            sB[a * 33 + e2] = Wo[i];
        }
        __syncthreads();
        for (int o = tid; o < 1024; o += 256) {
            int e1 = o >> 5, e2 = o & 31;
            float s = 0.f;
#pragma unroll 8
            for (int a = 0; a < 128; a++)
                s += sA[e1 * 128 + a] * sB[a * 33 + e2];
            g_Wvo[o] = s;
        }
    }
}

// ---------------------------------------------------------------------------
// Fused front + attention kernel (R13 structure + R14's inline histogram).
// ---------------------------------------------------------------------------
__device__ __forceinline__ unsigned score_key(float f) {
    unsigned u = __float_as_uint(f);
    return u ^ (((int)u >> 31) | 0x80000000u);
}
__device__ __forceinline__ float key_to_float(unsigned key) {
    unsigned u = (key & 0x80000000u) ? (key ^ 0x80000000u) : ~key;
    return __uint_as_float(u);
}

__global__ __launch_bounds__(256, 7)
void fa_kernel(const int* __restrict__ cats,
               const float* __restrict__ nums,
               const int* __restrict__ seqs,
               const int* __restrict__ tgt_ids,
               const float* __restrict__ cat_emb,
               const float* __restrict__ seq_emb,
               const float* __restrict__ Wnum,
               const float* __restrict__ bnum,
               const float* __restrict__ Wpool,
               const float* __restrict__ bpool,
               const float* __restrict__ bo) {
    int b = blockIdx.x;
    int tid  = threadIdx.x;
    int lane = tid & 31, warp = tid >> 5;
    __shared__ unsigned s_skey[LL];
    __shared__ int      s_hist[1024];      // aliased as s_ckey after phase C
    __shared__ int      s_cidx[1024];
    __shared__ float    s_cat[NCAT * EE];
    __shared__ float    s_tgt[EE];
    __shared__ float    s_part[8][EE];
    __shared__ float    s_qk[EE];
    __shared__ float    s_val[TOPK];
    __shared__ int      s_sel[TOPK];
    __shared__ float    s_w[TOPK];
    __shared__ float    s_pp[8][EE];
    __shared__ int      s_cnt;
    __shared__ int      s_thr;

    for (int i = tid; i < NCAT * EE; i += 256)
        s_cat[i] = cat_emb[(long)cats[b * NCAT + (i >> 5)] * EE + (i & 31)];
    if (tid < EE)
        s_tgt[tid] = cat_emb[(long)tgt_ids[b] * EE + tid];
    for (int i = tid; i < 1024; i += 256) s_hist[i] = 0;
    if (tid == 0) s_cnt = 0;
    __syncthreads();

    {
        int e = tid & 31, p = tid >> 5;
        float acc = 0.f;
#pragma unroll 4
        for (int i = p * 80; i < (p + 1) * 80; i++)
            acc += s_cat[i] * Wpool[i * EE + e];
        s_part[p][e] = acc;
    }
    __syncthreads();

    if (tid < EE) {
        int e = tid;
        float cp = bpool[e];
#pragma unroll
        for (int p = 0; p < 8; p++) cp += s_part[p][e];
        float ne = bnum[e];
#pragma unroll
        for (int j = 0; j < NNUM; j++) ne += nums[b * NNUM + j] * Wnum[j * EE + e];
        float qk = 0.f;
#pragma unroll
        for (int e2 = 0; e2 < EE; e2++) qk += s_tgt[e2] * g_Wqk[e2 * EE + e];
        float* fr = g_fused + (long)b * 128;
        fr[e]      = s_tgt[e];
        fr[64 + e] = cp;
        fr[96 + e] = ne;
        s_qk[e] = qk;
    }
    __syncthreads();

    const int* srow = seqs + (long)b * LL;

    // Phase A: scores -> keys + inline histogram
    {
        int g = tid >> 3;
        int c = tid & 7;
        float qk4[4] = { s_qk[c * 4 + 0], s_qk[c * 4 + 1], s_qk[c * 4 + 2], s_qk[c * 4 + 3] };
#pragma unroll 8
        for (int l0 = 0; l0 < LL; l0 += 32) {
            int l = l0 + g;
            int id = srow[l];
            float4 v = reinterpret_cast<const float4*>(seq_emb + (long)id * EE)[c];
            float s = qk4[0] * v.x + qk4[1] * v.y + qk4[2] * v.z + qk4[3] * v.w;
            s += __shfl_down_sync(0xffffffffu, s, 4, 8);
            s += __shfl_down_sync(0xffffffffu, s, 2, 8);
            s += __shfl_down_sync(0xffffffffu, s, 1, 8);
            if (c == 0) {
                unsigned key = score_key(s);
                s_skey[l] = key;
                atomicAdd(&s_hist[key >> 22], 1);
            }
        }
    }
    __syncthreads();

    // Phase C: threshold bin (warp 0)
    if (warp == 0) {
        int base = 1024 - (lane + 1) * 32;
        int s = 0;
#pragma unroll
        for (int i = 0; i < 32; i++) s += s_hist[base + i];
        int pre = s;
#pragma unroll
        for (int off = 1; off < 32; off <<= 1) {
            int o = __shfl_up_sync(0xffffffffu, pre, off);
            if (lane >= off) pre += o;
        }
        int preExcl = pre - s;
        if (pre >= TOPK && preExcl < TOPK) {
            int cum = preExcl;
            for (int i = 31; i >= 0; i--) {
                cum += s_hist[base + i];
                if (cum >= TOPK) { s_thr = base + i; break; }
            }
        }
    }
    __syncthreads();

    // Phase D: compact candidates (keys already stored)
    unsigned* s_ckey = (unsigned*)s_hist;
    unsigned thrkey = (unsigned)s_thr << 22;
    for (int i = tid; i < LL; i += 256) {
        unsigned key = s_skey[i];
        if (key >= thrkey) {
            int p = atomicAdd(&s_cnt, 1);
            s_ckey[p] = key;
            s_cidx[p] = i;
        }
    }
    __syncthreads();

    // Phase E: exact top-30 (warp 0, REDUX, tiebreak = min idx)
    if (warp == 0) {
        int m = s_cnt;
        if (m <= 96) {
            unsigned k0 = 0, k1 = 0, k2 = 0;
            unsigned i0 = 0xffffffffu, i1 = 0xffffffffu, i2 = 0xffffffffu;
            if (lane < m)      { k0 = s_ckey[lane];      i0 = (unsigned)s_cidx[lane]; }
            if (lane + 32 < m) { k1 = s_ckey[lane + 32]; i1 = (unsigned)s_cidx[lane + 32]; }
            if (lane + 64 < m) { k2 = s_ckey[lane + 64]; i2 = (unsigned)s_cidx[lane + 64]; }
#pragma unroll 1
            for (int k = 0; k < TOPK; k++) {
                unsigned bk = k0, bi = i0; int slot = 0;
                if (k1 > bk || (k1 == bk && i1 < bi)) { bk = k1; bi = i1; slot = 1; }
                if (k2 > bk || (k2 == bk && i2 < bi)) { bk = k2; bi = i2; slot = 2; }
                unsigned mxk = __reduce_max_sync(0xffffffffu, bk);
                unsigned cand = (bk == mxk) ? bi : 0xffffffffu;
                unsigned mni = __reduce_min_sync(0xffffffffu, cand);
                if (lane == 0) { s_val[k] = key_to_float(mxk); s_sel[k] = (int)mni; }
                if (bk == mxk && bi == mni) {
                    if (slot == 0)      { k0 = 0; i0 = 0xffffffffu; }
                    else if (slot == 1) { k1 = 0; i1 = 0xffffffffu; }
                    else                { k2 = 0; i2 = 0xffffffffu; }
                }
            }
        } else {
#pragma unroll 1
            for (int k = 0; k < TOPK; k++) {
                unsigned bk = 0, bi = 0xffffffffu; int bp = -1;
                for (int p = lane; p < m; p += 32) {
                    unsigned key = s_ckey[p]; unsigned ix = (unsigned)s_cidx[p];
                    if (key > bk || (key == bk && ix < bi)) { bk = key; bi = ix; bp = p; }
                }
                unsigned mxk = __reduce_max_sync(0xffffffffu, bk);
                unsigned cand = (bk == mxk) ? bi : 0xffffffffu;
                unsigned mni = __reduce_min_sync(0xffffffffu, cand);
                if (lane == 0) { s_val[k] = key_to_float(mxk); s_sel[k] = (int)mni; }
                if (bk == mxk && bi == mni) s_ckey[bp] = 0;
                __syncwarp();
            }
        }
        float mx = s_val[0];
        float e = (lane < TOPK) ? __expf(s_val[lane] - mx) : 0.f;
        float sum = e;
#pragma unroll
        for (int off = 16; off; off >>= 1) sum += __shfl_xor_sync(0xffffffffu, sum, off);
        if (lane < TOPK) s_w[lane] = e / sum;
    }
    __syncthreads();

    // Phase F: pooled + interest
    {
        float p = 0.f;
        for (int k = warp; k < TOPK; k += 8)
            p += s_w[k] * seq_emb[(long)srow[s_sel[k]] * EE + lane];
        s_pp[warp][lane] = p;
    }
    __syncthreads();

    if (tid < EE) {
        float p = s_pp[0][tid] + s_pp[1][tid] + s_pp[2][tid] + s_pp[3][tid] +
                  s_pp[4][tid] + s_pp[5][tid] + s_pp[6][tid] + s_pp[7][tid];
        s_pp[0][tid] = p;
    }
    __syncthreads();
    if (tid < EE) {
        float acc = bo[tid];
#pragma unroll
        for (int e = 0; e < EE; e++) acc += s_pp[0][e] * g_Wvo[e * EE + tid];
        g_fused[(long)b * 128 + EE + tid] = acc;
    }
}

// ---------------------------------------------------------------------------
// MLP tail (R13 version, the 80.3us champion): 512 threads = 8 pairs x 2
// warps; per-warp private 2-stage staging (32-row tiles), no mainloop
// barriers; pair sync only at reductions.
// ---------------------------------------------------------------------------
#define WSLOT 1024   // floats per stage per WARP (32 rows x 32 cols)

__device__ __forceinline__ void barpair(int pair) {
    asm volatile("bar.sync %0, 64;" :: "r"(pair + 1) : "memory");
}

__device__ __forceinline__ void fill_s32(const float* __restrict__ W, float* dst,
                                         int wcol0, int kbase, int t, int lane) {
#pragma unroll
    for (int it = 0; it < 8; it++) {
        int c = it * 32 + lane;             // 256 chunks of 16B
        int row = c >> 3, c4 = (c & 7) * 4;
        __pipeline_memcpy_async(dst + row * 32 + c4,
                                W + (kbase + t * 32 + row) * 256 + wcol0 + c4, 16);
    }
}
__device__ __forceinline__ void fill_d32(const float* __restrict__ Wa,
                                         const float* __restrict__ Wb, float* dst,
                                         int wcol0, int kbase, int t, int lane) {
#pragma unroll
    for (int it = 0; it < 8; it++) {
        int c = it * 32 + lane;
        int m = c >> 7, cr = c & 127;
        int row = cr >> 3, c4 = (cr & 7) * 4;
        const float* src = m ? Wb : Wa;
        __pipeline_memcpy_async(dst + m * 512 + row * 32 + c4,
                                src + (kbase + t * 16 + row) * 256 + wcol0 + c4, 16);
    }
}

template<int K>   // K = this warp's K-range
__device__ __forceinline__ void gemm_s(const float* __restrict__ W,
                                       const float* s_x, float* wbuf,
                                       int wcol0, int kbase, int lane, ull acc[4]) {
    constexpr int T = K / 32;
#pragma unroll
    for (int t = 0; t < T; t++) {
        if (t + 1 < T) {
            fill_s32(W, wbuf + ((t + 1) & 1) * WSLOT, wcol0, kbase, t + 1, lane);
            __pipeline_commit();
            __pipeline_wait_prior(1);
        } else {
            __pipeline_wait_prior(0);
        }
        __syncwarp();
        const float* bw = wbuf + (t & 1) * WSLOT;
        const float* xs = s_x + (kbase + t * 32) * 8;
#pragma unroll
        for (int i = 0; i < 32; i++) {
            ulonglong2 xa = *(const ulonglong2*)(xs + i * 8);
            ulonglong2 xb = *(const ulonglong2*)(xs + i * 8 + 4);
            ull wp = pack2s(bw[i * 32 + lane]);
            FMA2(acc[0], xa.x, wp, acc[0]);
            FMA2(acc[1], xa.y, wp, acc[1]);
            FMA2(acc[2], xb.x, wp, acc[2]);
            FMA2(acc[3], xb.y, wp, acc[3]);
        }
    }
}

__device__ __forceinline__ void gemm_d(const float* __restrict__ Wa,
                                       const float* __restrict__ Wb,
                                       const float* s_x, float* wbuf,
                                       int wcol0, int kbase, int lane,
                                       ull a1[4], ull a2[4]) {
    constexpr int T = 8;   // warp K-range 128, 16 rows per tile
#pragma unroll
    for (int t = 0; t < T; t++) {
        if (t + 1 < T) {
            fill_d32(Wa, Wb, wbuf + ((t + 1) & 1) * WSLOT, wcol0, kbase, t + 1, lane);
            __pipeline_commit();
            __pipeline_wait_prior(1);
        } else {
            __pipeline_wait_prior(0);
        }
        __syncwarp();
        const float* bwa = wbuf + (t & 1) * WSLOT;
        const float* bwb = bwa + 512;
        const float* xs = s_x + (kbase + t * 16) * 8;
#pragma unroll
        for (int i = 0; i < 16; i++) {
            ulonglong2 xa = *(const ulonglong2*)(xs + i * 8);
            ulonglong2 xb = *(const ulonglong2*)(xs + i * 8 + 4);
            ull w1 = pack2s(bwa[i * 32 + lane]);
            ull w2 = pack2s(bwb[i * 32 + lane]);
            FMA2(a1[0], xa.x, w1, a1[0]);
            FMA2(a1[1], xa.y, w1, a1[1]);
            FMA2(a1[2], xb.x, w1, a1[2]);
            FMA2(a1[3], xb.y, w1, a1[3]);
            FMA2(a2[0], xa.x, w2, a2[0]);
            FMA2(a2[1], xa.y, w2, a2[1]);
            FMA2(a2[2], xb.x, w2, a2[2]);
            FMA2(a2[3], xb.y, w2, a2[3]);
        }
    }
}

__global__ __launch_bounds__(512)
void mlp_kernel(const float* __restrict__ Wmlp, const float* __restrict__ bmlp,
                const float* __restrict__ W11, const float* __restrict__ b11,
                const float* __restrict__ W12, const float* __restrict__ b12,
                const float* __restrict__ W1p, const float* __restrict__ b1p,
                const float* __restrict__ W21, const float* __restrict__ b21,
                const float* __restrict__ W22, const float* __restrict__ b22,
                const float* __restrict__ W2p, const float* __restrict__ b2p,
                const float* __restrict__ Wout, const float* __restrict__ bout,
                float* __restrict__ out) {
    extern __shared__ float smem[];
    float* s_f = smem;                 // 128*8 interleaved [i][r]
    float* s_h = smem + 1024;          // 256*8 interleaved
    float* s_q = s_h + 2048;
    float* wall = s_q + 2048;          // 16 warps * 2 * WSLOT = 32768 floats
    ull*   red  = (ull*)(wall + 16 * 2 * WSLOT);   // 256 cols * 8 ull = 16KB

    int b0 = blockIdx.x * ROWS;
    int tid = threadIdx.x;
    int w = tid >> 5, lane = tid & 31;
    int pair = w >> 1, sub = w & 1;
    int wcol0 = pair * 32;
    int colg = wcol0 + lane;
    float* wbuf = wall + w * (2 * WSLOT);          // per-WARP private buffers
    ull* redc = red + (pair * 32 + lane) * 8;

    for (int idx = tid; idx < ROWS * 128; idx += 512) {
        int r = idx >> 7, i = idx & 127;
        s_f[i * 8 + r] = g_fused[(long)b0 * 128 + idx];
    }
    fill_s32(Wmlp, wbuf, wcol0, sub * 64, 0, lane);
    __pipeline_commit();
    __syncthreads();

    // h = relu(fused @ Wmlp + bmlp)   (warp K-range 64)
    {
        ull acc[4];
        ull bp = sub ? 0ull : pack2s(bmlp[colg]);
#pragma unroll
        for (int p = 0; p < 4; p++) acc[p] = bp;
        gemm_s<64>(Wmlp, s_f, wbuf, wcol0, sub * 64, lane, acc);
        if (sub) {
#pragma unroll
            for (int p = 0; p < 4; p++) redc[p] = acc[p];
        }
        barpair(pair);
        if (!sub) {
#pragma unroll
            for (int p = 0; p < 4; p++) {
                ADD2(acc[p], acc[p], redc[p]);
                float a, b;
                unpack2(acc[p], a, b);
                *(ull*)(s_h + colg * 8 + 2 * p) = pack2(fmaxf(a, 0.f), fmaxf(b, 0.f));
            }
        }
    }

    const float* Ws1[2] = { W11, W21 };  const float* Bs1[2] = { b11, b21 };
    const float* Ws2[2] = { W12, W22 };  const float* Bs2[2] = { b12, b22 };
    const float* Wsp[2] = { W1p, W2p };  const float* Bsp[2] = { b1p, b2p };

#pragma unroll
    for (int blk = 0; blk < 2; blk++) {
        fill_d32(Ws1[blk], Ws2[blk], wbuf, wcol0, sub * 128, 0, lane);
        __pipeline_commit();
        __syncthreads();   // publishes s_h

        ull a1[4], a2[4];
        ull bb1 = sub ? 0ull : pack2s(Bs1[blk][colg]);
        ull bb2 = sub ? 0ull : pack2s(Bs2[blk][colg]);
#pragma unroll
        for (int p = 0; p < 4; p++) { a1[p] = bb1; a2[p] = bb2; }
        gemm_d(Ws1[blk], Ws2[blk], s_h, wbuf, wcol0, sub * 128, lane, a1, a2);
        if (sub) {
#pragma unroll
            for (int p = 0; p < 4; p++) { redc[p] = a1[p]; redc[4 + p] = a2[p]; }
        }
        barpair(pair);
        if (!sub) {
#pragma unroll
            for (int p = 0; p < 4; p++) {
                ADD2(a1[p], a1[p], redc[p]);
                ADD2(a2[p], a2[p], redc[4 + p]);
                ull qp;
                MUL2(qp, a1[p], a2[p]);
                *(ull*)(s_q + colg * 8 + 2 * p) = qp;
            }
        }

        fill_s32(Wsp[blk], wbuf, wcol0, sub * 128, 0, lane);
        __pipeline_commit();
        __syncthreads();   // publishes s_q

        ull ap[4];
        ull bbp = sub ? 0ull : pack2s(Bsp[blk][colg]);
#pragma unroll
        for (int p = 0; p < 4; p++) ap[p] = bbp;
        gemm_s<128>(Wsp[blk], s_q, wbuf, wcol0, sub * 128, lane, ap);
        if (sub) {
#pragma unroll
            for (int p = 0; p < 4; p++) redc[p] = ap[p];
        }
        barpair(pair);
        if (!sub) {
#pragma unroll
            for (int p = 0; p < 4; p++) {
                ADD2(ap[p], ap[p], redc[p]);
                ull hp = *(ull*)(s_h + colg * 8 + 2 * p);
                ADD2(hp, hp, ap[p]);
                *(ull*)(s_h + colg * 8 + 2 * p) = hp;
            }
        }
    }
    __syncthreads();

    // out[b0+r] = sum_c h[r][c]*Wout[c] + bout (warps 0..7 reduce rows 0..7)
    if (w < 8) {
        float v = 0.f;
#pragma unroll
        for (int c = lane; c < HH; c += 32) v += s_h[c * 8 + w] * Wout[c];
#pragma unroll
        for (int off = 16; off; off >>= 1) v += __shfl_down_sync(0xffffffffu, v, off);
        if (lane == 0) out[b0 + w] = v + bout[0];
    }
}

// ---------------------------------------------------------------------------
extern "C" void kernel_launch(void* const* d_in, const int* in_sizes, int n_in,
                              void* d_out, int out_size) {
    const int*   cats    = (const int*)  d_in[0];
    const float* nums    = (const float*)d_in[1];
    const int*   seqs    = (const int*)  d_in[2];
    const int*   tgt_ids = (const int*)  d_in[3];
    const float* cat_emb = (const float*)d_in[4];
    const float* seq_emb = (const float*)d_in[5];
    const float* Wnum    = (const float*)d_in[6];
    const float* bnum    = (const float*)d_in[7];
    const float* Wq      = (const float*)d_in[8];
    const float* Wk      = (const float*)d_in[9];
    const float* Wv      = (const float*)d_in[10];
    const float* Wo      = (const float*)d_in[11];
    const float* bo      = (const float*)d_in[12];
    const float* Wpool   = (const float*)d_in[13];
    const float* bpool   = (const float*)d_in[14];
    const float* Wmlp    = (const float*)d_in[15];
    const float* bmlp    = (const float*)d_in[16];
    const float* q1_W1   = (const float*)d_in[17];
    const float* q1_b1   = (const float*)d_in[18];
    const float* q1_W2   = (const float*)d_in[19];
    const float* q1_b2   = (const float*)d_in[20];
    const float* q1_Wp   = (const float*)d_in[21];
    const float* q1_bp   = (const float*)d_in[22];
    const float* q2_W1   = (const float*)d_in[23];
    const float* q2_b1   = (const float*)d_in[24];
    const float* q2_W2   = (const float*)d_in[25];
    const float* q2_b2   = (const float*)d_in[26];
    const float* q2_Wp   = (const float*)d_in[27];
    const float* q2_bp   = (const float*)d_in[28];
    const float* Wout    = (const float*)d_in[29];
    const float* bout    = (const float*)d_in[30];
    float* out = (float*)d_out;

    const int mlp_smem = (1024 + 2048 + 2048 + 16 * 2 * WSLOT) * sizeof(float) + 16384;
    cudaFuncSetAttribute(mlp_kernel, cudaFuncAttributeMaxDynamicSharedMemorySize, mlp_smem);

    precompute_kernel<<<2, 256>>>(Wq, Wk, Wv, Wo);
    fa_kernel<<<BB, 256>>>(cats, nums, seqs, tgt_ids, cat_emb, seq_emb,
                           Wnum, bnum, Wpool, bpool, bo);
    mlp_kernel<<<BB / ROWS, 512, mlp_smem>>>(
        Wmlp, bmlp,
        q1_W1, q1_b1, q1_W2, q1_b2, q1_Wp, q1_bp,
        q2_W1, q2_b1, q2_W2, q2_b2, q2_Wp, q2_bp,
        Wout, bout, out);
}

// round 16
// speedup vs baseline: 1.2155x; 1.1135x over previous
#include <cuda_runtime.h>
#include <cuda_pipeline.h>
#include <math.h>

// Problem constants
#define BB    1024
#define LL    1024
#define NCAT  20
#define NNUM  10
#define EE    32
#define HH    256
#define TOPK  30
#define ROWS  8

typedef unsigned long long ull;

__device__ __forceinline__ ull pack2s(float v) {
    ull r; asm("mov.b64 %0, {%1, %1};" : "=l"(r) : "f"(v)); return r;
}
__device__ __forceinline__ ull pack2(float a, float b) {
    ull r; asm("mov.b64 %0, {%1, %2};" : "=l"(r) : "f"(a), "f"(b)); return r;
}
__device__ __forceinline__ void unpack2(ull p, float& a, float& b) {
    asm("mov.b64 {%0, %1}, %2;" : "=f"(a), "=f"(b) : "l"(p));
}
#define FMA2(d, a, b, c) asm("fma.rn.f32x2 %0, %1, %2, %3;" : "=l"(d) : "l"(a), "l"(b), "l"(c))
#define MUL2(d, a, b)    asm("mul.rn.f32x2 %0, %1, %2;"     : "=l"(d) : "l"(a), "l"(b))
#define ADD2(d, a, b)    asm("add.rn.f32x2 %0, %1, %2;"     : "=l"(d) : "l"(a), "l"(b))

// Device scratch
__device__ float g_fused[BB * 128];
__device__ float g_Wqk[EE * EE];
__device__ float g_Wvo[EE * EE];
__device__ unsigned g_epoch;   // zero-init; +2 per launch (producers)

__device__ __forceinline__ unsigned score_key(float f) {
    unsigned u = __float_as_uint(f);
    return u ^ (((int)u >> 31) | 0x80000000u);
}
__device__ __forceinline__ float key_to_float(unsigned key) {
    unsigned u = (key & 0x80000000u) ? (key ^ 0x80000000u) : ~key;
    return __uint_as_float(u);
}

// ---------------------------------------------------------------------------
// Fused kernel: blocks 0-1 = precompute producers; blocks 2..1025 = fa rows.
// ---------------------------------------------------------------------------
__global__ __launch_bounds__(256, 7)
void fa_kernel(const int* __restrict__ cats,
               const float* __restrict__ nums,
               const int* __restrict__ seqs,
               const int* __restrict__ tgt_ids,
               const float* __restrict__ cat_emb,
               const float* __restrict__ seq_emb,
               const float* __restrict__ Wnum,
               const float* __restrict__ bnum,
               const float* __restrict__ Wpool,
               const float* __restrict__ bpool,
               const float* __restrict__ bo,
               const float* __restrict__ Wq,
               const float* __restrict__ Wk,
               const float* __restrict__ Wv,
               const float* __restrict__ Wo) {
    int tid  = threadIdx.x;
    int lane = tid & 31, warp = tid >> 5;
    __shared__ float    s_pool4[4352];     // skey|hist|cidx for fa; sB for producers
    __shared__ float    s_cat[NCAT * EE];
    __shared__ float    s_tgt[EE];
    __shared__ float    s_part[8][EE];
    __shared__ float    s_qk[EE];
    __shared__ float    s_val[TOPK];
    __shared__ int      s_sel[TOPK];
    __shared__ float    s_w[TOPK];
    __shared__ float    s_pp[8][EE];
    __shared__ int      s_cnt;
    __shared__ int      s_thr;

    // ===== Producer blocks: compute fused 32x32 matrices, signal epoch =====
    if (blockIdx.x < 2) {
        float* sB = s_pool4;               // [128][33] padded, 4224 floats
        if (blockIdx.x == 0) {
            for (int i = tid; i < 4096; i += 256) {
                int e2 = i >> 7, a = i & 127;          // Wk[e2][a] coalesced
                sB[a * 33 + e2] = Wk[i];
            }
            __syncthreads();
            for (int o = tid; o < 1024; o += 256) {
                int e1 = o >> 5, e2 = o & 31;          // e1 warp-uniform
                float s = 0.f;
#pragma unroll 8
                for (int a = 0; a < 128; a++)
                    s += Wq[e1 * 128 + a] * sB[a * 33 + e2];
                g_Wqk[o] = s * 0.08838834764831845f;   // 1/sqrt(128)
            }
        } else {
            for (int i = tid; i < 4096; i += 256) {
                int a = i >> 5, e2 = i & 31;           // Wo[a][e2] coalesced
                sB[a * 33 + e2] = Wo[i];
            }
            __syncthreads();
            for (int o = tid; o < 1024; o += 256) {
                int e1 = o >> 5, e2 = o & 31;
                float s = 0.f;
#pragma unroll 8
                for (int a = 0; a < 128; a++)
                    s += Wv[e1 * 128 + a] * sB[a * 33 + e2];
                g_Wvo[o] = s;
            }
        }
        __syncthreads();
        if (tid == 0) {
            __threadfence();
            atomicAdd(&g_epoch, 1u);
        }
        return;
    }

    int b = blockIdx.x - 2;
    unsigned* s_skey = (unsigned*)s_pool4;           // [1024]
    int*      s_hist = (int*)(s_pool4 + 1024);       // [1024]
    int*      s_cidx = (int*)(s_pool4 + 2048);       // [1024]

    // ===== FRONT: gathers (independent of g_Wqk) =====
    for (int i = tid; i < NCAT * EE; i += 256)
        s_cat[i] = cat_emb[(long)cats[b * NCAT + (i >> 5)] * EE + (i & 31)];
    if (tid < EE)
        s_tgt[tid] = cat_emb[(long)tgt_ids[b] * EE + tid];
    for (int i = tid; i < 1024; i += 256) s_hist[i] = 0;
    if (tid == 0) s_cnt = 0;
    __syncthreads();

    {
        int e = tid & 31, p = tid >> 5;
        float acc = 0.f;
#pragma unroll 4
        for (int i = p * 80; i < (p + 1) * 80; i++)
            acc += s_cat[i] * Wpool[i * EE + e];
        s_part[p][e] = acc;
    }
    __syncthreads();

    // wait for producers (only spins on the first launch; epoch persists)
    if (tid == 0) {
        while (atomicAdd(&g_epoch, 0u) < 2u) { }
        __threadfence();
    }
    __syncthreads();

    if (tid < EE) {
        int e = tid;
        float cp = bpool[e];
#pragma unroll
        for (int p = 0; p < 8; p++) cp += s_part[p][e];
        float ne = bnum[e];
#pragma unroll
        for (int j = 0; j < NNUM; j++) ne += nums[b * NNUM + j] * Wnum[j * EE + e];
        float qk = 0.f;
#pragma unroll
        for (int e2 = 0; e2 < EE; e2++) qk += s_tgt[e2] * g_Wqk[e2 * EE + e];
        float* fr = g_fused + (long)b * 128;
        fr[e]      = s_tgt[e];
        fr[64 + e] = cp;
        fr[96 + e] = ne;
        s_qk[e] = qk;
    }
    __syncthreads();

    const int* srow = seqs + (long)b * LL;

    // Phase A: scores -> keys + inline histogram
    {
        int g = tid >> 3;
        int c = tid & 7;
        float qk4[4] = { s_qk[c * 4 + 0], s_qk[c * 4 + 1], s_qk[c * 4 + 2], s_qk[c * 4 + 3] };
#pragma unroll 8
        for (int l0 = 0; l0 < LL; l0 += 32) {
            int l = l0 + g;
            int id = srow[l];
            float4 v = reinterpret_cast<const float4*>(seq_emb + (long)id * EE)[c];
            float s = qk4[0] * v.x + qk4[1] * v.y + qk4[2] * v.z + qk4[3] * v.w;
            s += __shfl_down_sync(0xffffffffu, s, 4, 8);
            s += __shfl_down_sync(0xffffffffu, s, 2, 8);
            s += __shfl_down_sync(0xffffffffu, s, 1, 8);
            if (c == 0) {
                unsigned key = score_key(s);
                s_skey[l] = key;
                atomicAdd(&s_hist[key >> 22], 1);
            }
        }
    }
    __syncthreads();

    // Phase C: threshold bin (warp 0)
    if (warp == 0) {
        int base = 1024 - (lane + 1) * 32;
        int s = 0;
#pragma unroll
        for (int i = 0; i < 32; i++) s += s_hist[base + i];
        int pre = s;
#pragma unroll
        for (int off = 1; off < 32; off <<= 1) {
            int o = __shfl_up_sync(0xffffffffu, pre, off);
            if (lane >= off) pre += o;
        }
        int preExcl = pre - s;
        if (pre >= TOPK && preExcl < TOPK) {
            int cum = preExcl;
            for (int i = 31; i >= 0; i--) {
                cum += s_hist[base + i];
                if (cum >= TOPK) { s_thr = base + i; break; }
            }
        }
    }
    __syncthreads();

    // Phase D: compact candidates (keys stored; hist region dead -> reuse)
    unsigned* s_ckey = (unsigned*)s_hist;
    unsigned thrkey = (unsigned)s_thr << 22;
    for (int i = tid; i < LL; i += 256) {
        unsigned key = s_skey[i];
        if (key >= thrkey) {
            int p = atomicAdd(&s_cnt, 1);
            s_ckey[p] = key;
            s_cidx[p] = i;
        }
    }
    __syncthreads();

    // Phase E: exact top-30 (warp 0, REDUX, tiebreak = min idx)
    if (warp == 0) {
        int m = s_cnt;
        if (m <= 96) {
            unsigned k0 = 0, k1 = 0, k2 = 0;
            unsigned i0 = 0xffffffffu, i1 = 0xffffffffu, i2 = 0xffffffffu;
            if (lane < m)      { k0 = s_ckey[lane];      i0 = (unsigned)s_cidx[lane]; }
            if (lane + 32 < m) { k1 = s_ckey[lane + 32]; i1 = (unsigned)s_cidx[lane + 32]; }
            if (lane + 64 < m) { k2 = s_ckey[lane + 64]; i2 = (unsigned)s_cidx[lane + 64]; }
#pragma unroll 1
            for (int k = 0; k < TOPK; k++) {
                unsigned bk = k0, bi = i0; int slot = 0;
                if (k1 > bk || (k1 == bk && i1 < bi)) { bk = k1; bi = i1; slot = 1; }
                if (k2 > bk || (k2 == bk && i2 < bi)) { bk = k2; bi = i2; slot = 2; }
                unsigned mxk = __reduce_max_sync(0xffffffffu, bk);
                unsigned cand = (bk == mxk) ? bi : 0xffffffffu;
                unsigned mni = __reduce_min_sync(0xffffffffu, cand);
                if (lane == 0) { s_val[k] = key_to_float(mxk); s_sel[k] = (int)mni; }
                if (bk == mxk && bi == mni) {
                    if (slot == 0)      { k0 = 0; i0 = 0xffffffffu; }
                    else if (slot == 1) { k1 = 0; i1 = 0xffffffffu; }
                    else                { k2 = 0; i2 = 0xffffffffu; }
                }
            }
        } else {
#pragma unroll 1
            for (int k = 0; k < TOPK; k++) {
                unsigned bk = 0, bi = 0xffffffffu; int bp = -1;
                for (int p = lane; p < m; p += 32) {
                    unsigned key = s_ckey[p]; unsigned ix = (unsigned)s_cidx[p];
                    if (key > bk || (key == bk && ix < bi)) { bk = key; bi = ix; bp = p; }
                }
                unsigned mxk = __reduce_max_sync(0xffffffffu, bk);
                unsigned cand = (bk == mxk) ? bi : 0xffffffffu;
                unsigned mni = __reduce_min_sync(0xffffffffu, cand);
                if (lane == 0) { s_val[k] = key_to_float(mxk); s_sel[k] = (int)mni; }
                if (bk == mxk && bi == mni) s_ckey[bp] = 0;
                __syncwarp();
            }
        }
        float mx = s_val[0];
        float e = (lane < TOPK) ? __expf(s_val[lane] - mx) : 0.f;
        float sum = e;
#pragma unroll
        for (int off = 16; off; off >>= 1) sum += __shfl_xor_sync(0xffffffffu, sum, off);
        if (lane < TOPK) s_w[lane] = e / sum;
    }
    __syncthreads();

    // Phase F: pooled + interest
    {
        float p = 0.f;
        for (int k = warp; k < TOPK; k += 8)
            p += s_w[k] * seq_emb[(long)srow[s_sel[k]] * EE + lane];
        s_pp[warp][lane] = p;
    }
    __syncthreads();

    if (tid < EE) {
        float p = s_pp[0][tid] + s_pp[1][tid] + s_pp[2][tid] + s_pp[3][tid] +
                  s_pp[4][tid] + s_pp[5][tid] + s_pp[6][tid] + s_pp[7][tid];
        s_pp[0][tid] = p;
    }
    __syncthreads();
    if (tid < EE) {
        float acc = bo[tid];
#pragma unroll
        for (int e = 0; e < EE; e++) acc += s_pp[0][e] * g_Wvo[e * EE + tid];
        g_fused[(long)b * 128 + EE + tid] = acc;
    }
}

// ---------------------------------------------------------------------------
// MLP tail (R13 champion, unchanged): 512 threads = 8 pairs x 2 warps;
// per-warp private 2-stage staging (32-row tiles); no mainloop barriers.
// ---------------------------------------------------------------------------
#define WSLOT 1024

__device__ __forceinline__ void barpair(int pair) {
    asm volatile("bar.sync %0, 64;" :: "r"(pair + 1) : "memory");
}

__device__ __forceinline__ void fill_s32(const float* __restrict__ W, float* dst,
                                         int wcol0, int kbase, int t, int lane) {
#pragma unroll
    for (int it = 0; it < 8; it++) {
        int c = it * 32 + lane;
        int row = c >> 3, c4 = (c & 7) * 4;
        __pipeline_memcpy_async(dst + row * 32 + c4,
                                W + (kbase + t * 32 + row) * 256 + wcol0 + c4, 16);
    }
}
__device__ __forceinline__ void fill_d32(const float* __restrict__ Wa,
                                         const float* __restrict__ Wb, float* dst,
                                         int wcol0, int kbase, int t, int lane) {
#pragma unroll
    for (int it = 0; it < 8; it++) {
        int c = it * 32 + lane;
        int m = c >> 7, cr = c & 127;
        int row = cr >> 3, c4 = (cr & 7) * 4;
        const float* src = m ? Wb : Wa;
        __pipeline_memcpy_async(dst + m * 512 + row * 32 + c4,
                                src + (kbase + t * 16 + row) * 256 + wcol0 + c4, 16);
    }
}

template<int K>
__device__ __forceinline__ void gemm_s(const float* __restrict__ W,
                                       const float* s_x, float* wbuf,
                                       int wcol0, int kbase, int lane, ull acc[4]) {
    constexpr int T = K / 32;
#pragma unroll
    for (int t = 0; t < T; t++) {
        if (t + 1 < T) {
            fill_s32(W, wbuf + ((t + 1) & 1) * WSLOT, wcol0, kbase, t + 1, lane);
            __pipeline_commit();
            __pipeline_wait_prior(1);
        } else {
            __pipeline_wait_prior(0);
        }
        __syncwarp();
        const float* bw = wbuf + (t & 1) * WSLOT;
        const float* xs = s_x + (kbase + t * 32) * 8;
#pragma unroll
        for (int i = 0; i < 32; i++) {
            ulonglong2 xa = *(const ulonglong2*)(xs + i * 8);
            ulonglong2 xb = *(const ulonglong2*)(xs + i * 8 + 4);
            ull wp = pack2s(bw[i * 32 + lane]);
            FMA2(acc[0], xa.x, wp, acc[0]);
            FMA2(acc[1], xa.y, wp, acc[1]);
            FMA2(acc[2], xb.x, wp, acc[2]);
            FMA2(acc[3], xb.y, wp, acc[3]);
        }
    }
}

__device__ __forceinline__ void gemm_d(const float* __restrict__ Wa,
                                       const float* __restrict__ Wb,
                                       const float* s_x, float* wbuf,
                                       int wcol0, int kbase, int lane,
                                       ull a1[4], ull a2[4]) {
    constexpr int T = 8;
#pragma unroll
    for (int t = 0; t < T; t++) {
        if (t + 1 < T) {
            fill_d32(Wa, Wb, wbuf + ((t + 1) & 1) * WSLOT, wcol0, kbase, t + 1, lane);
            __pipeline_commit();
            __pipeline_wait_prior(1);
        } else {
            __pipeline_wait_prior(0);
        }
        __syncwarp();
        const float* bwa = wbuf + (t & 1) * WSLOT;
        const float* bwb = bwa + 512;
        const float* xs = s_x + (kbase + t * 16) * 8;
#pragma unroll
        for (int i = 0; i < 16; i++) {
            ulonglong2 xa = *(const ulonglong2*)(xs + i * 8);
            ulonglong2 xb = *(const ulonglong2*)(xs + i * 8 + 4);
            ull w1 = pack2s(bwa[i * 32 + lane]);
            ull w2 = pack2s(bwb[i * 32 + lane]);
            FMA2(a1[0], xa.x, w1, a1[0]);
            FMA2(a1[1], xa.y, w1, a1[1]);
            FMA2(a1[2], xb.x, w1, a1[2]);
            FMA2(a1[3], xb.y, w1, a1[3]);
            FMA2(a2[0], xa.x, w2, a2[0]);
            FMA2(a2[1], xa.y, w2, a2[1]);
            FMA2(a2[2], xb.x, w2, a2[2]);
            FMA2(a2[3], xb.y, w2, a2[3]);
        }
    }
}

__global__ __launch_bounds__(512)
void mlp_kernel(const float* __restrict__ Wmlp, const float* __restrict__ bmlp,
                const float* __restrict__ W11, const float* __restrict__ b11,
                const float* __restrict__ W12, const float* __restrict__ b12,
                const float* __restrict__ W1p, const float* __restrict__ b1p,
                const float* __restrict__ W21, const float* __restrict__ b21,
                const float* __restrict__ W22, const float* __restrict__ b22,
                const float* __restrict__ W2p, const float* __restrict__ b2p,
                const float* __restrict__ Wout, const float* __restrict__ bout,
                float* __restrict__ out) {
    extern __shared__ float smem[];
    float* s_f = smem;
    float* s_h = smem + 1024;
    float* s_q = s_h + 2048;
    float* wall = s_q + 2048;
    ull*   red  = (ull*)(wall + 16 * 2 * WSLOT);

    int b0 = blockIdx.x * ROWS;
    int tid = threadIdx.x;
    int w = tid >> 5, lane = tid & 31;
    int pair = w >> 1, sub = w & 1;
    int wcol0 = pair * 32;
    int colg = wcol0 + lane;
    float* wbuf = wall + w * (2 * WSLOT);
    ull* redc = red + (pair * 32 + lane) * 8;

    for (int idx = tid; idx < ROWS * 128; idx += 512) {
        int r = idx >> 7, i = idx & 127;
        s_f[i * 8 + r] = g_fused[(long)b0 * 128 + idx];
    }
    fill_s32(Wmlp, wbuf, wcol0, sub * 64, 0, lane);
    __pipeline_commit();
    __syncthreads();

    {
        ull acc[4];
        ull bp = sub ? 0ull : pack2s(bmlp[colg]);
#pragma unroll
        for (int p = 0; p < 4; p++) acc[p] = bp;
        gemm_s<64>(Wmlp, s_f, wbuf, wcol0, sub * 64, lane, acc);
        if (sub) {
#pragma unroll
            for (int p = 0; p < 4; p++) redc[p] = acc[p];
        }
        barpair(pair);
        if (!sub) {
#pragma unroll
            for (int p = 0; p < 4; p++) {
                ADD2(acc[p], acc[p], redc[p]);
                float a, b;
                unpack2(acc[p], a, b);
                *(ull*)(s_h + colg * 8 + 2 * p) = pack2(fmaxf(a, 0.f), fmaxf(b, 0.f));
            }
        }
    }

    const float* Ws1[2] = { W11, W21 };  const float* Bs1[2] = { b11, b21 };
    const float* Ws2[2] = { W12, W22 };  const float* Bs2[2] = { b12, b22 };
    const float* Wsp[2] = { W1p, W2p };  const float* Bsp[2] = { b1p, b2p };

#pragma unroll
    for (int blk = 0; blk < 2; blk++) {
        fill_d32(Ws1[blk], Ws2[blk], wbuf, wcol0, sub * 128, 0, lane);
        __pipeline_commit();
        __syncthreads();

        ull a1[4], a2[4];
        ull bb1 = sub ? 0ull : pack2s(Bs1[blk][colg]);
        ull bb2 = sub ? 0ull : pack2s(Bs2[blk][colg]);
#pragma unroll
        for (int p = 0; p < 4; p++) { a1[p] = bb1; a2[p] = bb2; }
        gemm_d(Ws1[blk], Ws2[blk], s_h, wbuf, wcol0, sub * 128, lane, a1, a2);
        if (sub) {
#pragma unroll
            for (int p = 0; p < 4; p++) { redc[p] = a1[p]; redc[4 + p] = a2[p]; }
        }
        barpair(pair);
        if (!sub) {
#pragma unroll
            for (int p = 0; p < 4; p++) {
                ADD2(a1[p], a1[p], redc[p]);
                ADD2(a2[p], a2[p], redc[4 + p]);
                ull qp;
                MUL2(qp, a1[p], a2[p]);
                *(ull*)(s_q + colg * 8 + 2 * p) = qp;
            }
        }

        fill_s32(Wsp[blk], wbuf, wcol0, sub * 128, 0, lane);
        __pipeline_commit();
        __syncthreads();

        ull ap[4];
        ull bbp = sub ? 0ull : pack2s(Bsp[blk][colg]);
#pragma unroll
        for (int p = 0; p < 4; p++) ap[p] = bbp;
        gemm_s<128>(Wsp[blk], s_q, wbuf, wcol0, sub * 128, lane, ap);
        if (sub) {
#pragma unroll
            for (int p = 0; p < 4; p++) redc[p] = ap[p];
        }
        barpair(pair);
        if (!sub) {
#pragma unroll
            for (int p = 0; p < 4; p++) {
                ADD2(ap[p], ap[p], redc[p]);
                ull hp = *(ull*)(s_h + colg * 8 + 2 * p);
                ADD2(hp, hp, ap[p]);
                *(ull*)(s_h + colg * 8 + 2 * p) = hp;
            }
        }
    }
    __syncthreads();

    if (w < 8) {
        float v = 0.f;
#pragma unroll
        for (int c = lane; c < HH; c += 32) v += s_h[c * 8 + w] * Wout[c];
#pragma unroll
        for (int off = 16; off; off >>= 1) v += __shfl_down_sync(0xffffffffu, v, off);
        if (lane == 0) out[b0 + w] = v + bout[0];
    }
}

// ---------------------------------------------------------------------------
extern "C" void kernel_launch(void* const* d_in, const int* in_sizes, int n_in,
                              void* d_out, int out_size) {
    const int*   cats    = (const int*)  d_in[0];
    const float* nums    = (const float*)d_in[1];
    const int*   seqs    = (const int*)  d_in[2];
    const int*   tgt_ids = (const int*)  d_in[3];
    const float* cat_emb = (const float*)d_in[4];
    const float* seq_emb = (const float*)d_in[5];
    const float* Wnum    = (const float*)d_in[6];
    const float* bnum    = (const float*)d_in[7];
    const float* Wq      = (const float*)d_in[8];
    const float* Wk      = (const float*)d_in[9];
    const float* Wv      = (const float*)d_in[10];
    const float* Wo      = (const float*)d_in[11];
    const float* bo      = (const float*)d_in[12];
    const float* Wpool   = (const float*)d_in[13];
    const float* bpool   = (const float*)d_in[14];
    const float* Wmlp    = (const float*)d_in[15];
    const float* bmlp    = (const float*)d_in[16];
    const float* q1_W1   = (const float*)d_in[17];
    const float* q1_b1   = (const float*)d_in[18];
    const float* q1_W2   = (const float*)d_in[19];
    const float* q1_b2   = (const float*)d_in[20];
    const float* q1_Wp   = (const float*)d_in[21];
    const float* q1_bp   = (const float*)d_in[22];
    const float* q2_W1   = (const float*)d_in[23];
    const float* q2_b1   = (const float*)d_in[24];
    const float* q2_W2   = (const float*)d_in[25];
    const float* q2_b2   = (const float*)d_in[26];
    const float* q2_Wp   = (const float*)d_in[27];
    const float* q2_bp   = (const float*)d_in[28];
    const float* Wout    = (const float*)d_in[29];
    const float* bout    = (const float*)d_in[30];
    float* out = (float*)d_out;

    const int mlp_smem = (1024 + 2048 + 2048 + 16 * 2 * WSLOT) * sizeof(float) + 16384;
    cudaFuncSetAttribute(mlp_kernel, cudaFuncAttributeMaxDynamicSharedMemorySize, mlp_smem);

    fa_kernel<<<BB + 2, 256>>>(cats, nums, seqs, tgt_ids, cat_emb, seq_emb,
                               Wnum, bnum, Wpool, bpool, bo, Wq, Wk, Wv, Wo);
    mlp_kernel<<<BB / ROWS, 512, mlp_smem>>>(
        Wmlp, bmlp,
        q1_W1, q1_b1, q1_W2, q1_b2, q1_Wp, q1_bp,
        q2_W1, q2_b1, q2_W2, q2_b2, q2_Wp, q2_bp,
        Wout, bout, out);
}